// round 13
// baseline (speedup 1.0000x reference)
#include <cuda_runtime.h>

#define DD    32          // embedding dim D
#define MM    32          // memories per hop
#define LEAKY 0.2f

// scratch: Rh[slot*D + d] for hop>=1 slots; hop-0 logits precomputed
__device__ float g_Rh[131072 * 32];
__device__ float g_logit0[131072];     // logit0[slot] for slot < B*M

__device__ __forceinline__ float warpSum(float v) {
    #pragma unroll
    for (int off = 16; off; off >>= 1) v += __shfl_xor_sync(0xffffffffu, v, off);
    return v;
}
__device__ __forceinline__ float warpMax(float v) {
    #pragma unroll
    for (int off = 16; off; off >>= 1) v = fmaxf(v, __shfl_xor_sync(0xffffffffu, v, off));
    return v;
}

// ---------------------------------------------------------------------------
// K1: everything ripple depends on. blockIdx ranges:
//   [0, RB)     : r_all gather + fused Rh / hop0-logit (warp-per-slot)
//   [+TB)       : t_all gather (leaky)
//   [rest)      : iEmbed base copy (ripple scatters over it in K2)
// ZERO shared memory -> full L1D carveout -> rel table gets L1 hits.
// ---------------------------------------------------------------------------
__global__ void __launch_bounds__(256) mega_kernel(
        const int*    __restrict__ pos,
        const int*    __restrict__ mh,
        const int*    __restrict__ mr,
        const int*    __restrict__ mt,
        const float4* __restrict__ iE4,
        const float4* __restrict__ ent4,
        const float4* __restrict__ rel4,
        float4* __restrict__ out_i4,
        float4* __restrict__ out_t4,
        float4* __restrict__ out_r4,
        int HBM, int RB, int TB, int Ie4, int BM) {
    int blk = blockIdx.x;
    const float* ent = (const float*)ent4;
    const float* iE  = (const float*)iE4;
    const unsigned FULL = 0xffffffffu;

    if (blk < RB) {
        // ---- r_all gather + Rh = R@h, one warp per slot, register-only ----
        int warp = threadIdx.x >> 5, lane = threadIdx.x & 31;
        int slot = blk * 8 + warp;
        if (slot >= HBM) return;

        int r = __ldg(&mr[slot]);
        const float4* src = rel4 + (size_t)r * 256;
        float4* dst = out_r4 + (size_t)slot * 256;

        float4 v[8];
        #pragma unroll
        for (int k = 0; k < 8; k++)       // 8 outstanding loads (L1/L2)
            v[k] = __ldg(&src[k * 32 + lane]);

        int e = __ldg(&mh[slot]);
        float hval = __ldg(&ent[(size_t)e * DD + lane]);

        // h4 = h[4c..4c+3], c = lane&7  (v[k] covers R[4k+(lane>>3)][4c..4c+3])
        int c4 = (lane & 7) * 4;
        float hx = __shfl_sync(FULL, hval, c4 + 0);
        float hy = __shfl_sync(FULL, hval, c4 + 1);
        float hz = __shfl_sync(FULL, hval, c4 + 2);
        float hw = __shfl_sync(FULL, hval, c4 + 3);

        float p[8];
        #pragma unroll
        for (int k = 0; k < 8; k++) {
            __stcs(&dst[k * 32 + lane], v[k]);   // streaming write-out
            p[k] = v[k].x * hx + v[k].y * hy + v[k].z * hz + v[k].w * hw;
        }
        #pragma unroll
        for (int k = 0; k < 8; k++) {
            p[k] += __shfl_xor_sync(FULL, p[k], 1);
            p[k] += __shfl_xor_sync(FULL, p[k], 2);
            p[k] += __shfl_xor_sync(FULL, p[k], 4);
        }
        // permutation: lane d wants row d, held in p[d>>2] on lanes 8(d&3)+..
        int myk = lane & 7;
        float temp = p[0];
        #pragma unroll
        for (int k = 1; k < 8; k++) if (myk == k) temp = p[k];
        float acc = __shfl_sync(FULL, temp, ((lane & 3) << 3) + (lane >> 2));

        if (slot < BM) {
            // hop 0: fold in item0 = iE[pos[b]] -> scalar logit, skip g_Rh
            int b = slot / MM;
            int p0 = __ldg(&pos[b]);
            float it0 = __ldg(&iE[(size_t)p0 * DD + lane]);   // L1-hot row
            float lg = warpSum(acc * it0);
            if (lane == 0) g_logit0[slot] = lg;
        } else {
            g_Rh[(size_t)slot * DD + lane] = acc;
        }
    } else if (blk < RB + TB) {
        // ---- t_all gather (ripple dependency) ----
        int tid = (blk - RB) * 256 + threadIdx.x;
        if (tid < HBM * 8) {
            int slot = tid >> 3, j = tid & 7;
            int e = __ldg(&mt[slot]);
            float4 v = __ldg(&ent4[(size_t)e * 8 + j]);
            v.x = v.x > 0.f ? v.x : LEAKY * v.x;
            v.y = v.y > 0.f ? v.y : LEAKY * v.y;
            v.z = v.z > 0.f ? v.z : LEAKY * v.z;
            v.w = v.w > 0.f ? v.w : LEAKY * v.w;
            out_t4[slot * 8 + j] = v;     // re-read by ripple: keep cacheable
        }
    } else {
        // ---- iEmbed base copy (must precede ripple's scatter = K2) ----
        int j = (blk - RB - TB) * 256 + threadIdx.x;
        if (j < Ie4)
            out_i4[j] = __ldg(&iE4[j]);
    }
}

// ---------------------------------------------------------------------------
// K2: ripple blocks FIRST (256), then h-gather + uE-copy backfill blocks that
// keep the memory system busy while ripple's few blocks chew latency.
//   [0, RP)     : ripple hops + scatter (one warp per b, 8 warps/block)
//   [+HB2)      : h_all gather
//   [rest)      : uEmbed copy
// ---------------------------------------------------------------------------
__global__ void __launch_bounds__(256) ripple_kernel(
        const int*    __restrict__ pos,
        const float*  __restrict__ iE,
        const float*  __restrict__ t_all,
        const float*  __restrict__ W,
        const int*    __restrict__ mh,
        const float4* __restrict__ uE4,
        const float4* __restrict__ ent4,
        float*  __restrict__ out_i,
        float4* __restrict__ out_h4,
        float4* __restrict__ out_u4,
        int B, int nhop, int HBM, int RP, int HB2, int Ue4) {
    __shared__ float sW[DD * DD];
    __shared__ float sRh[8][DD * DD];   // per-warp Rh tile (hop>=1)
    __shared__ float sIt[8][DD];
    int blk = blockIdx.x;

    if (blk >= RP) {
        if (blk < RP + HB2) {
            // ---- h_all gather (backfill) ----
            int tid = (blk - RP) * 256 + threadIdx.x;
            if (tid < HBM * 8) {
                int slot = tid >> 3, j = tid & 7;
                int e = __ldg(&mh[slot]);
                __stcs(&out_h4[slot * 8 + j], __ldg(&ent4[(size_t)e * 8 + j]));
            }
        } else {
            // ---- uEmbed copy (backfill) ----
            int j = (blk - RP - HB2) * 256 + threadIdx.x;
            if (j < Ue4)
                __stcs(&out_u4[j], __ldg(&uE4[j]));
        }
        return;
    }

    // ---- ripple ----
    for (int i = threadIdx.x; i < DD * DD; i += blockDim.x) sW[i] = W[i];
    __syncthreads();
    int warp = threadIdx.x >> 5, lane = threadIdx.x & 31;
    int b = blk * 8 + warp;
    if (b >= B) return;
    int p = pos[b];

    // last-wins: if any later batch element maps to the same item, we lose.
    bool dup = false;
    for (int j = b + 1 + lane; j < B; j += 32) dup |= (pos[j] == p);
    if (__any_sync(0xffffffffu, dup)) return;

    float* myRh = sRh[warp];
    float* myIt = sIt[warp];

    // front-load hop-1 Rh tile + logit0 + item (10 loads in flight)
    if (nhop > 1) {
        const float4* Rh4 = (const float4*)(g_Rh + (size_t)(B + b) * MM * DD);
        #pragma unroll
        for (int j = 0; j < 8; j++)
            ((float4*)myRh)[j * 32 + lane] = __ldg(&Rh4[j * 32 + lane]);
    }
    float logit = __ldg(&g_logit0[(size_t)b * MM + lane]);
    float item = __ldg(&iE[(size_t)p * DD + lane]);

    for (int hop = 0; hop < nhop; hop++) {
        if (hop > 0) {
            if (hop > 1) {   // generic fallback for nhop>2 (unused @nhop=2)
                const float4* Rh4 =
                    (const float4*)(g_Rh + (size_t)(hop * B + b) * MM * DD);
                #pragma unroll
                for (int j = 0; j < 8; j++)
                    ((float4*)myRh)[j * 32 + lane] = __ldg(&Rh4[j * 32 + lane]);
            }
            myIt[lane] = item;
            __syncwarp();
            // logit[m] on lane m: 4 partial accumulators, 8-deep chains
            float l0 = 0.f, l1 = 0.f, l2 = 0.f, l3 = 0.f;
            #pragma unroll
            for (int i = 0; i < DD; i += 4) {
                int e0 = (i + 0 + lane) & (DD - 1);
                int e1 = (i + 1 + lane) & (DD - 1);
                int e2 = (i + 2 + lane) & (DD - 1);
                int e3 = (i + 3 + lane) & (DD - 1);
                l0 = fmaf(myRh[lane * DD + e0], myIt[e0], l0);
                l1 = fmaf(myRh[lane * DD + e1], myIt[e1], l1);
                l2 = fmaf(myRh[lane * DD + e2], myIt[e2], l2);
                l3 = fmaf(myRh[lane * DD + e3], myIt[e3], l3);
            }
            logit = (l0 + l1) + (l2 + l3);
        }
        // softmax across lanes
        float mx = warpMax(logit);
        float ex = expf(logit - mx);
        float prob = ex / warpSum(ex);
        // o[d] = sum_m prob[m] * t[m][d] : 4 partial accumulators
        const float* tb = t_all + (size_t)(hop * B + b) * MM * DD;
        float o0 = 0.f, o1 = 0.f, o2 = 0.f, o3 = 0.f;
        #pragma unroll
        for (int m = 0; m < MM; m += 4) {
            float pa = __shfl_sync(0xffffffffu, prob, m + 0);
            float pb = __shfl_sync(0xffffffffu, prob, m + 1);
            float pc = __shfl_sync(0xffffffffu, prob, m + 2);
            float pd = __shfl_sync(0xffffffffu, prob, m + 3);
            o0 = fmaf(pa, __ldg(&tb[(m + 0) * DD + lane]), o0);
            o1 = fmaf(pb, __ldg(&tb[(m + 1) * DD + lane]), o1);
            o2 = fmaf(pc, __ldg(&tb[(m + 2) * DD + lane]), o2);
            o3 = fmaf(pd, __ldg(&tb[(m + 3) * DD + lane]), o3);
        }
        float o = (o0 + o1) + (o2 + o3);
        // item = (item + o) @ W.T via smem broadcast, 4 partials
        __syncwarp();
        myIt[lane] = item + o;
        __syncwarp();
        float n0 = 0.f, n1 = 0.f, n2 = 0.f, n3 = 0.f;
        #pragma unroll
        for (int e = 0; e < DD; e += 4) {
            int e0 = (e + 0 + lane) & (DD - 1);
            int e1 = (e + 1 + lane) & (DD - 1);
            int e2 = (e + 2 + lane) & (DD - 1);
            int e3 = (e + 3 + lane) & (DD - 1);
            n0 = fmaf(myIt[e0], sW[lane * DD + e0], n0);
            n1 = fmaf(myIt[e1], sW[lane * DD + e1], n1);
            n2 = fmaf(myIt[e2], sW[lane * DD + e2], n2);
            n3 = fmaf(myIt[e3], sW[lane * DD + e3], n3);
        }
        item = (n0 + n1) + (n2 + n3);
        __syncwarp();
    }
    out_i[(size_t)p * DD + lane] = item;
}

// ---------------------------------------------------------------------------
extern "C" void kernel_launch(void* const* d_in, const int* in_sizes, int n_in,
                              void* d_out, int out_size) {
    const int*   pos = (const int*)d_in[0];
    const int*   mh  = (const int*)d_in[1];
    const int*   mr  = (const int*)d_in[2];
    const int*   mt  = (const int*)d_in[3];
    const float* uE  = (const float*)d_in[4];
    const float* iE  = (const float*)d_in[5];
    const float* ent = (const float*)d_in[6];
    const float* rel = (const float*)d_in[7];
    const float* W   = (const float*)d_in[8];
    float* out = (float*)d_out;

    const int B    = in_sizes[0];             // 2048
    const int HBM  = in_sizes[1];             // H*B*M = 131072
    const int nhop = HBM / (B * MM);          // 2
    const int BM   = B * MM;                  // 65536
    const size_t Ue = (size_t)in_sizes[4];    // USER*D floats
    const size_t Ie = (size_t)in_sizes[5];    // ITEM*D floats

    float* out_u = out;
    float* out_i = out_u + Ue;
    float* out_h = out_i + Ie;
    float* out_t = out_h + (size_t)HBM * DD;
    float* out_r = out_t + (size_t)HBM * DD;

    const int RB  = (HBM + 7) / 8;                 // 16384 r-blocks
    const int TB  = (HBM * 8 + 255) / 256;         // 4096 t-blocks
    const int Ue4 = (int)(Ue / 4), Ie4 = (int)(Ie / 4);
    const int IB  = (Ie4 + 255) / 256;             // 3125 iE-copy blocks
    const int RP  = (B + 7) / 8;                   // 256 ripple blocks
    const int HB2 = (HBM * 8 + 255) / 256;         // 4096 h-blocks
    const int UB  = (Ue4 + 255) / 256;             // 3125 uE-copy blocks

    mega_kernel<<<RB + TB + IB, 256>>>(
        pos, mh, mr, mt,
        (const float4*)iE, (const float4*)ent, (const float4*)rel,
        (float4*)out_i, (float4*)out_t, (float4*)out_r,
        HBM, RB, TB, Ie4, BM);

    ripple_kernel<<<RP + HB2 + UB, 256>>>(
        pos, iE, out_t, W, mh,
        (const float4*)uE, (const float4*)ent,
        out_i, (float4*)out_h, (float4*)out_u,
        B, nhop, HBM, RP, HB2, Ue4);
}

// round 14
// speedup vs baseline: 1.0452x; 1.0452x over previous
#include <cuda_runtime.h>
#include <cstdint>

#define DD    32          // embedding dim D
#define MM    32          // memories per hop
#define LEAKY 0.2f
#define RW    4           // ripple warps per block

// scratch: Rh[slot*D + d] for hop>=1 slots; hop-0 logits precomputed
__device__ float g_Rh[131072 * 32];
__device__ float g_logit0[131072];     // logit0[slot] for slot < B*M

__device__ __forceinline__ float warpSum(float v) {
    #pragma unroll
    for (int off = 16; off; off >>= 1) v += __shfl_xor_sync(0xffffffffu, v, off);
    return v;
}
__device__ __forceinline__ float warpMax(float v) {
    #pragma unroll
    for (int off = 16; off; off >>= 1) v = fmaxf(v, __shfl_xor_sync(0xffffffffu, v, off));
    return v;
}
__device__ __forceinline__ void cp16(uint32_t saddr, const void* gaddr) {
    asm volatile("cp.async.cg.shared.global [%0], [%1], 16;" :: "r"(saddr), "l"(gaddr));
}

// ---------------------------------------------------------------------------
// MEGA kernel (R12 version, measured best): blockIdx ranges select role.
//   [0, RB)          : r_all gather + fused Rh (warp-per-slot, 8 slots/block)
//                      hop-0 slots fold in item0 -> scalar logit0 (skip g_Rh)
//   [RB, RB+HB)      : h_all / t_all gather (float4 granularity)
//   [RB+HB, ...)     : uEmbed + iEmbed contiguous copy (float4)
// ZERO shared memory -> full 228KB L1D carveout -> rel table gets L1 hits.
// ---------------------------------------------------------------------------
__global__ void __launch_bounds__(256) mega_kernel(
        const int*    __restrict__ pos,
        const int*    __restrict__ mh,
        const int*    __restrict__ mr,
        const int*    __restrict__ mt,
        const float4* __restrict__ uE4,
        const float4* __restrict__ iE4,
        const float4* __restrict__ ent4,
        const float4* __restrict__ rel4,
        float4* __restrict__ out_u4,
        float4* __restrict__ out_h4,
        float4* __restrict__ out_t4,
        float4* __restrict__ out_r4,
        int HBM, int RB, int HB, int Ue4, int Ie4, int BM) {
    int blk = blockIdx.x;
    const float* ent = (const float*)ent4;
    const float* iE  = (const float*)iE4;
    const unsigned FULL = 0xffffffffu;

    if (blk < RB) {
        int warp = threadIdx.x >> 5, lane = threadIdx.x & 31;
        int slot = blk * 8 + warp;
        if (slot >= HBM) return;

        int r = __ldg(&mr[slot]);
        const float4* src = rel4 + (size_t)r * 256;
        float4* dst = out_r4 + (size_t)slot * 256;

        float4 v[8];
        #pragma unroll
        for (int k = 0; k < 8; k++)
            v[k] = __ldg(&src[k * 32 + lane]);

        int e = __ldg(&mh[slot]);
        float hval = __ldg(&ent[(size_t)e * DD + lane]);

        int c4 = (lane & 7) * 4;
        float hx = __shfl_sync(FULL, hval, c4 + 0);
        float hy = __shfl_sync(FULL, hval, c4 + 1);
        float hz = __shfl_sync(FULL, hval, c4 + 2);
        float hw = __shfl_sync(FULL, hval, c4 + 3);

        float p[8];
        #pragma unroll
        for (int k = 0; k < 8; k++) {
            __stcs(&dst[k * 32 + lane], v[k]);
            p[k] = v[k].x * hx + v[k].y * hy + v[k].z * hz + v[k].w * hw;
        }
        #pragma unroll
        for (int k = 0; k < 8; k++) {
            p[k] += __shfl_xor_sync(FULL, p[k], 1);
            p[k] += __shfl_xor_sync(FULL, p[k], 2);
            p[k] += __shfl_xor_sync(FULL, p[k], 4);
        }
        int myk = lane & 7;
        float temp = p[0];
        #pragma unroll
        for (int k = 1; k < 8; k++) if (myk == k) temp = p[k];
        float acc = __shfl_sync(FULL, temp, ((lane & 3) << 3) + (lane >> 2));

        if (slot < BM) {
            int b = slot / MM;
            int p0 = __ldg(&pos[b]);
            float it0 = __ldg(&iE[(size_t)p0 * DD + lane]);
            float lg = warpSum(acc * it0);
            if (lane == 0) g_logit0[slot] = lg;
        } else {
            g_Rh[(size_t)slot * DD + lane] = acc;
        }
    } else if (blk < RB + HB) {
        int tid = (blk - RB) * 256 + threadIdx.x;
        int N = HBM * 8;
        if (tid < N) {
            int slot = tid >> 3, j = tid & 7;
            int e = __ldg(&mh[slot]);
            __stcs(&out_h4[slot * 8 + j], __ldg(&ent4[(size_t)e * 8 + j]));
        } else if (tid < 2 * N) {
            int t2 = tid - N;
            int slot = t2 >> 3, j = t2 & 7;
            int e = __ldg(&mt[slot]);
            float4 v = __ldg(&ent4[(size_t)e * 8 + j]);
            v.x = v.x > 0.f ? v.x : LEAKY * v.x;
            v.y = v.y > 0.f ? v.y : LEAKY * v.y;
            v.z = v.z > 0.f ? v.z : LEAKY * v.z;
            v.w = v.w > 0.f ? v.w : LEAKY * v.w;
            out_t4[slot * 8 + j] = v;
        }
    } else {
        int j = (blk - RB - HB) * 256 + threadIdx.x;
        if (j < Ue4)
            __stcs(&out_u4[j], __ldg(&uE4[j]));
        else if (j < Ue4 + Ie4)
            __stcs(&out_u4[j], __ldg(&iE4[j - Ue4]));
    }
}

// ---------------------------------------------------------------------------
// Ripple: one warp per b, 4 warps/block, 48KB smem. ALL memory the warp will
// ever need (hop-1 Rh tile, hop-0 t, hop-1 t = 24 lines) is issued as
// cp.async at instruction 0 -> ONE DRAM round-trip, overlapped with the
// dup-scan and hop-0 softmax. Compute then runs entirely from smem/L1.
// ---------------------------------------------------------------------------
__global__ void __launch_bounds__(128) ripple_kernel(
        const int*   __restrict__ pos,
        const float* __restrict__ iE,
        const float* __restrict__ t_all,
        const float* __restrict__ W,
        float* __restrict__ out_i,
        int B, int nhop) {
    __shared__ float sRh[RW][MM * DD];   // 16KB
    __shared__ float sT0[RW][MM * DD];   // 16KB
    __shared__ float sT1[RW][MM * DD];   // 16KB  (total 48KB)
    const unsigned FULL = 0xffffffffu;
    int warp = threadIdx.x >> 5, lane = threadIdx.x & 31;
    int b = blockIdx.x * RW + warp;
    if (b >= B) return;
    int p = __ldg(&pos[b]);

    // issue ALL prefetches first: hop-1 Rh, hop-0 t, hop-1 t (24 cp.async)
    {
        const float4* Rh4 = (const float4*)(g_Rh + (size_t)(B + b) * MM * DD);
        const float4* T0  = (const float4*)(t_all + (size_t)b * MM * DD);
        const float4* T1  = (const float4*)(t_all + (size_t)(B + b) * MM * DD);
        uint32_t aR = (uint32_t)__cvta_generic_to_shared(&sRh[warp][0]);
        uint32_t a0 = (uint32_t)__cvta_generic_to_shared(&sT0[warp][0]);
        uint32_t a1 = (uint32_t)__cvta_generic_to_shared(&sT1[warp][0]);
        #pragma unroll
        for (int j = 0; j < 8; j++) {
            cp16(a0 + (j * 32 + lane) * 16, &T0[j * 32 + lane]);
            cp16(aR + (j * 32 + lane) * 16, &Rh4[j * 32 + lane]);
            cp16(a1 + (j * 32 + lane) * 16, &T1[j * 32 + lane]);
        }
        asm volatile("cp.async.commit_group;");
    }

    float logit = __ldg(&g_logit0[(size_t)b * MM + lane]);
    float item = __ldg(&iE[(size_t)p * DD + lane]);

    // last-wins dup scan overlaps the async loads (pos is L1-hot, 8KB)
    bool dup = false;
    for (int j = b + 1 + lane; j < B; j += 32) dup |= (__ldg(&pos[j]) == p);
    if (__any_sync(FULL, dup)) {
        asm volatile("cp.async.wait_group 0;" ::: "memory");  // drain safely
        return;
    }

    const float* myRh = sRh[warp];
    for (int hop = 0; hop < nhop; hop++) {
        if (hop > 0) {
            if (hop > 1) {   // generic fallback for nhop>2 (unused @nhop=2)
                float* dRh = sRh[warp];
                float* dT1 = sT1[warp];
                const float4* Rh4 =
                    (const float4*)(g_Rh + (size_t)(hop * B + b) * MM * DD);
                const float4* T4 =
                    (const float4*)(t_all + (size_t)(hop * B + b) * MM * DD);
                #pragma unroll
                for (int j = 0; j < 8; j++) {
                    ((float4*)dRh)[j * 32 + lane] = __ldg(&Rh4[j * 32 + lane]);
                    ((float4*)dT1)[j * 32 + lane] = __ldg(&T4[j * 32 + lane]);
                }
                __syncwarp();
            }
            // logit[m] on lane m from smem Rh x shuffled item, 4 partials
            float l0 = 0.f, l1 = 0.f, l2 = 0.f, l3 = 0.f;
            #pragma unroll
            for (int i = 0; i < DD; i += 4) {
                int e0 = (i + 0 + lane) & (DD - 1);
                int e1 = (i + 1 + lane) & (DD - 1);
                int e2 = (i + 2 + lane) & (DD - 1);
                int e3 = (i + 3 + lane) & (DD - 1);
                l0 = fmaf(myRh[lane * DD + e0], __shfl_sync(FULL, item, e0), l0);
                l1 = fmaf(myRh[lane * DD + e1], __shfl_sync(FULL, item, e1), l1);
                l2 = fmaf(myRh[lane * DD + e2], __shfl_sync(FULL, item, e2), l2);
                l3 = fmaf(myRh[lane * DD + e3], __shfl_sync(FULL, item, e3), l3);
            }
            logit = (l0 + l1) + (l2 + l3);
        }
        // softmax across lanes
        float mx = warpMax(logit);
        float ex = expf(logit - mx);
        float prob = ex / warpSum(ex);

        if (hop == 0) {  // first consumption of smem tiles
            asm volatile("cp.async.wait_group 0;" ::: "memory");
            __syncwarp();
        }
        const float* tb = (hop == 0) ? sT0[warp] : sT1[warp];
        float o0 = 0.f, o1 = 0.f, o2 = 0.f, o3 = 0.f;
        #pragma unroll
        for (int m = 0; m < MM; m += 4) {
            float pa = __shfl_sync(FULL, prob, m + 0);
            float pb = __shfl_sync(FULL, prob, m + 1);
            float pc = __shfl_sync(FULL, prob, m + 2);
            float pd = __shfl_sync(FULL, prob, m + 3);
            o0 = fmaf(pa, tb[(m + 0) * DD + lane], o0);
            o1 = fmaf(pb, tb[(m + 1) * DD + lane], o1);
            o2 = fmaf(pc, tb[(m + 2) * DD + lane], o2);
            o3 = fmaf(pd, tb[(m + 3) * DD + lane], o3);
        }
        float o = (o0 + o1) + (o2 + o3);

        // item = (item + o) @ W.T : x broadcast via shuffle, W via L1 (__ldg)
        float x = item + o;
        float n0 = 0.f, n1 = 0.f, n2 = 0.f, n3 = 0.f;
        #pragma unroll
        for (int e = 0; e < DD; e += 4) {
            int e0 = (e + 0 + lane) & (DD - 1);
            int e1 = (e + 1 + lane) & (DD - 1);
            int e2 = (e + 2 + lane) & (DD - 1);
            int e3 = (e + 3 + lane) & (DD - 1);
            n0 = fmaf(__shfl_sync(FULL, x, e0), __ldg(&W[lane * DD + e0]), n0);
            n1 = fmaf(__shfl_sync(FULL, x, e1), __ldg(&W[lane * DD + e1]), n1);
            n2 = fmaf(__shfl_sync(FULL, x, e2), __ldg(&W[lane * DD + e2]), n2);
            n3 = fmaf(__shfl_sync(FULL, x, e3), __ldg(&W[lane * DD + e3]), n3);
        }
        item = (n0 + n1) + (n2 + n3);
    }
    out_i[(size_t)p * DD + lane] = item;
}

// ---------------------------------------------------------------------------
extern "C" void kernel_launch(void* const* d_in, const int* in_sizes, int n_in,
                              void* d_out, int out_size) {
    const int*   pos = (const int*)d_in[0];
    const int*   mh  = (const int*)d_in[1];
    const int*   mr  = (const int*)d_in[2];
    const int*   mt  = (const int*)d_in[3];
    const float* uE  = (const float*)d_in[4];
    const float* iE  = (const float*)d_in[5];
    const float* ent = (const float*)d_in[6];
    const float* rel = (const float*)d_in[7];
    const float* W   = (const float*)d_in[8];
    float* out = (float*)d_out;

    const int B    = in_sizes[0];             // 2048
    const int HBM  = in_sizes[1];             // H*B*M = 131072
    const int nhop = HBM / (B * MM);          // 2
    const int BM   = B * MM;                  // 65536
    const size_t Ue = (size_t)in_sizes[4];    // USER*D floats
    const size_t Ie = (size_t)in_sizes[5];    // ITEM*D floats

    float* out_u = out;
    float* out_i = out_u + Ue;
    float* out_h = out_i + Ie;
    float* out_t = out_h + (size_t)HBM * DD;
    float* out_r = out_t + (size_t)HBM * DD;

    const int RB  = (HBM + 7) / 8;                      // 16384 r-blocks
    const int HB  = (2 * HBM * 8 + 255) / 256;          // 8192 ht-blocks
    const int Ue4 = (int)(Ue / 4), Ie4 = (int)(Ie / 4);
    const int CB  = (Ue4 + Ie4 + 255) / 256;            // 6250 copy-blocks

    mega_kernel<<<RB + HB + CB, 256>>>(
        pos, mh, mr, mt,
        (const float4*)uE, (const float4*)iE,
        (const float4*)ent, (const float4*)rel,
        (float4*)out_u, (float4*)out_h, (float4*)out_t, (float4*)out_r,
        HBM, RB, HB, Ue4, Ie4, BM);

    ripple_kernel<<<(B + RW - 1) / RW, 128>>>(pos, iE, out_t, W, out_i, B, nhop);
}